// round 3
// baseline (speedup 1.0000x reference)
#include <cuda_runtime.h>
#include <math.h>

#define B_ 4
#define N1_ 16384
#define N2_ 4096
#define C1_ 128
#define C2_ 256
#define O1_ 256
#define O2_ 128
#define ROWS_TOT (B_ * N1_)

// ---------------- scratch ----------------------------------------------------
__device__ int   g_idx[B_ * N1_ * 3];
__device__ float g_w  [B_ * N1_ * 3];
__device__ float g_W1t[384 * O1_];               // [c][o]
__device__ float g_W2t[O1_ * O2_];               // [c][o]
__device__ float g_Zt [B_ * N2_ * O1_];          // [b][m][o]
__device__ float g_y1 [B_ * O1_ * N1_];          // [b][o][n]  channel-major
__device__ float g_y2 [B_ * O2_ * N1_];          // [b][o][n]  channel-major
__device__ float g_s1[O1_], g_q1[O1_], g_scale1[O1_], g_shift1[O1_];
__device__ float g_s2[O2_], g_q2[O2_], g_scale2[O2_], g_shift2[O2_];

// ---------------- 0) weight transpose ---------------------------------------
__global__ void wtrans(const float* __restrict__ W1, const float* __restrict__ W2) {
    int i = blockIdx.x * 256 + threadIdx.x;
    if (i < 384 * 256) { int o = i / 384, c = i % 384; g_W1t[c * O1_ + o] = W1[i]; }
    if (i < 256 * 128) { int o = i / 256, c = i % 256; g_W2t[c * O2_ + o] = W2[i]; }
}

// ---------------- 1) 3-NN (2 queries/thread, float4 candidates) -------------
__global__ void knn_kernel(const float* __restrict__ xyz1,
                           const float* __restrict__ xyz2) {
    const int b = blockIdx.y;
    const int tid = threadIdx.x;
    const int na = blockIdx.x * 256 + tid;
    const int nb = na + 128;
    __shared__ float4 sc[1024];

    const float* X1 = xyz1 + (size_t)b * 3 * N1_;
    const float* X2 = xyz2 + (size_t)b * 3 * N2_;
    const float ax = X1[na], ay = X1[N1_ + na], az = X1[2 * N1_ + na];
    const float bx = X1[nb], by = X1[N1_ + nb], bz = X1[2 * N1_ + nb];

    float A0 = 3.4e38f, A1 = 3.4e38f, A2 = 3.4e38f; int Ai0 = 0, Ai1 = 0, Ai2 = 0;
    float B0 = 3.4e38f, B1 = 3.4e38f, B2 = 3.4e38f; int Bi0 = 0, Bi1 = 0, Bi2 = 0;

    for (int t = 0; t < N2_ / 1024; t++) {
        __syncthreads();
        for (int j = tid; j < 1024; j += 128) {
            int g = t * 1024 + j;
            sc[j] = make_float4(X2[g], X2[N2_ + g], X2[2 * N2_ + g], 0.f);
        }
        __syncthreads();
        #pragma unroll 4
        for (int j = 0; j < 1024; j++) {
            float4 p = sc[j];
            int jj = t * 1024 + j;
            {
                float dx = ax - p.x, dy = ay - p.y, dz = az - p.z;
                float d = fmaf(dx, dx, fmaf(dy, dy, dz * dz));
                if (d < A2) {
                    if (d < A1) {
                        A2 = A1; Ai2 = Ai1;
                        if (d < A0) { A1 = A0; Ai1 = Ai0; A0 = d; Ai0 = jj; }
                        else        { A1 = d;  Ai1 = jj; }
                    } else { A2 = d; Ai2 = jj; }
                }
            }
            {
                float dx = bx - p.x, dy = by - p.y, dz = bz - p.z;
                float d = fmaf(dx, dx, fmaf(dy, dy, dz * dz));
                if (d < B2) {
                    if (d < B1) {
                        B2 = B1; Bi2 = Bi1;
                        if (d < B0) { B1 = B0; Bi1 = Bi0; B0 = d; Bi0 = jj; }
                        else        { B1 = d;  Bi1 = jj; }
                    } else { B2 = d; Bi2 = jj; }
                }
            }
        }
    }
    {
        float d0 = fmaxf(A0, 1e-10f), d1 = fmaxf(A1, 1e-10f), d2 = fmaxf(A2, 1e-10f);
        float w0 = 1.f / d0, w1 = 1.f / d1, w2 = 1.f / d2;
        float inv = 1.f / (w0 + w1 + w2);
        size_t base = ((size_t)b * N1_ + na) * 3;
        g_idx[base] = Ai0; g_idx[base + 1] = Ai1; g_idx[base + 2] = Ai2;
        g_w[base] = w0 * inv; g_w[base + 1] = w1 * inv; g_w[base + 2] = w2 * inv;
    }
    {
        float d0 = fmaxf(B0, 1e-10f), d1 = fmaxf(B1, 1e-10f), d2 = fmaxf(B2, 1e-10f);
        float w0 = 1.f / d0, w1 = 1.f / d1, w2 = 1.f / d2;
        float inv = 1.f / (w0 + w1 + w2);
        size_t base = ((size_t)b * N1_ + nb) * 3;
        g_idx[base] = Bi0; g_idx[base + 1] = Bi1; g_idx[base + 2] = Bi2;
        g_w[base] = w0 * inv; g_w[base + 1] = w1 * inv; g_w[base + 2] = w2 * inv;
    }
}

// ---------------- 2) zero stats ---------------------------------------------
__global__ void zero_stats() {
    int t = threadIdx.x;
    if (t < O1_) { g_s1[t] = 0.f; g_q1[t] = 0.f; }
    if (t < O2_) { g_s2[t] = 0.f; g_q2[t] = 0.f; }
}

// ---------------- 3) Zt[b][m][o] = W1b . p2 ---------------------------------
// grid (N2/128, O1/128, B), block 256, 8x8 microtile
__global__ void __launch_bounds__(256) zt_gemm(const float* __restrict__ p2) {
    const int b = blockIdx.z, ot = blockIdx.y, mt = blockIdx.x;
    __shared__ __align__(16) float As[16][128];
    __shared__ __align__(16) float Bs[16][128];
    const int tid = threadIdx.x, tx = tid & 15, ty = tid >> 4;
    float acc[8][8] = {};

    const float* Ab = p2 + (size_t)b * C2_ * N2_ + mt * 128;
    const float* Bb = g_W1t + 128 * O1_ + ot * 128;   // rows c=128..383

    for (int kc = 0; kc < C2_ / 16; kc++) {
        #pragma unroll
        for (int r = 0; r < 2; r++) {
            int e = tid + r * 256, row = e >> 5, c4 = (e & 31) * 4;
            *(float4*)&As[row][c4] = *(const float4*)&Ab[(size_t)(kc * 16 + row) * N2_ + c4];
            *(float4*)&Bs[row][c4] = *(const float4*)&Bb[(size_t)(kc * 16 + row) * O1_ + c4];
        }
        __syncthreads();
        #pragma unroll
        for (int k = 0; k < 16; k++) {
            float4 a0 = *(float4*)&As[k][tx * 4];
            float4 a1 = *(float4*)&As[k][tx * 4 + 64];
            float4 b0 = *(float4*)&Bs[k][ty * 4];
            float4 b1 = *(float4*)&Bs[k][ty * 4 + 64];
            float an[8] = {a0.x, a0.y, a0.z, a0.w, a1.x, a1.y, a1.z, a1.w};
            float ob[8] = {b0.x, b0.y, b0.z, b0.w, b1.x, b1.y, b1.z, b1.w};
            #pragma unroll
            for (int i = 0; i < 8; i++)
                #pragma unroll
                for (int j = 0; j < 8; j++) acc[i][j] = fmaf(an[i], ob[j], acc[i][j]);
        }
        __syncthreads();
    }
    #pragma unroll
    for (int i = 0; i < 8; i++) {
        int m = (i < 4) ? tx * 4 + i : 64 + tx * 4 + i - 4;
        float* row = g_Zt + ((size_t)b * N2_ + mt * 128 + m) * O1_ + ot * 128;
        *(float4*)&row[ty * 4]      = make_float4(acc[i][0], acc[i][1], acc[i][2], acc[i][3]);
        *(float4*)&row[ty * 4 + 64] = make_float4(acc[i][4], acc[i][5], acc[i][6], acc[i][7]);
    }
}

// ---------------- 4) GEMM1 + gather + fused BN1 stats ------------------------
// grid (N1/128, O1/128, B), block 256
__global__ void __launch_bounds__(256) gemm1(const float* __restrict__ p1,
                                             const float* __restrict__ b1) {
    const int b = blockIdx.z, ot = blockIdx.y, nt = blockIdx.x;
    __shared__ __align__(16) float As[16][128];
    __shared__ __align__(16) float Bs[16][128];
    __shared__ int   sidx[128][3];
    __shared__ float sw[128][3];
    __shared__ float red_s[128], red_q[128];
    const int tid = threadIdx.x, tx = tid & 15, ty = tid >> 4;
    float acc[8][8] = {};

    if (tid < 128) {
        size_t base = ((size_t)b * N1_ + nt * 128 + tid) * 3;
        #pragma unroll
        for (int k = 0; k < 3; k++) { sidx[tid][k] = g_idx[base + k]; sw[tid][k] = g_w[base + k]; }
        red_s[tid] = 0.f; red_q[tid] = 0.f;
    }

    const float* Ab = p1 + (size_t)b * C1_ * N1_ + nt * 128;
    const float* Bb = g_W1t + ot * 128;

    for (int kc = 0; kc < C1_ / 16; kc++) {
        #pragma unroll
        for (int r = 0; r < 2; r++) {
            int e = tid + r * 256, row = e >> 5, c4 = (e & 31) * 4;
            *(float4*)&As[row][c4] = *(const float4*)&Ab[(size_t)(kc * 16 + row) * N1_ + c4];
            *(float4*)&Bs[row][c4] = *(const float4*)&Bb[(size_t)(kc * 16 + row) * O1_ + c4];
        }
        __syncthreads();
        #pragma unroll
        for (int k = 0; k < 16; k++) {
            float4 a0 = *(float4*)&As[k][tx * 4];
            float4 a1 = *(float4*)&As[k][tx * 4 + 64];
            float4 b0 = *(float4*)&Bs[k][ty * 4];
            float4 b1 = *(float4*)&Bs[k][ty * 4 + 64];
            float an[8] = {a0.x, a0.y, a0.z, a0.w, a1.x, a1.y, a1.z, a1.w};
            float ob[8] = {b0.x, b0.y, b0.z, b0.w, b1.x, b1.y, b1.z, b1.w};
            #pragma unroll
            for (int i = 0; i < 8; i++)
                #pragma unroll
                for (int j = 0; j < 8; j++) acc[i][j] = fmaf(an[i], ob[j], acc[i][j]);
        }
        __syncthreads();
    }

    // epilogue: bias + 3-NN gather
    float bias[8];
    #pragma unroll
    for (int j = 0; j < 8; j++) {
        int o = (j < 4) ? ty * 4 + j : 64 + ty * 4 + j - 4;
        bias[j] = b1[ot * 128 + o];
    }
    const float* Ztb = g_Zt + (size_t)b * N2_ * O1_ + ot * 128;
    #pragma unroll
    for (int i = 0; i < 8; i++) {
        int nl = (i < 4) ? tx * 4 + i : 64 + tx * 4 + i - 4;
        #pragma unroll
        for (int j = 0; j < 8; j++) acc[i][j] += bias[j];
        #pragma unroll
        for (int k = 0; k < 3; k++) {
            const float* z = Ztb + (size_t)sidx[nl][k] * O1_;
            float wv = sw[nl][k];
            float4 z0 = *(const float4*)&z[ty * 4];
            float4 z1 = *(const float4*)&z[ty * 4 + 64];
            acc[i][0] = fmaf(wv, z0.x, acc[i][0]); acc[i][1] = fmaf(wv, z0.y, acc[i][1]);
            acc[i][2] = fmaf(wv, z0.z, acc[i][2]); acc[i][3] = fmaf(wv, z0.w, acc[i][3]);
            acc[i][4] = fmaf(wv, z1.x, acc[i][4]); acc[i][5] = fmaf(wv, z1.y, acc[i][5]);
            acc[i][6] = fmaf(wv, z1.z, acc[i][6]); acc[i][7] = fmaf(wv, z1.w, acc[i][7]);
        }
    }

    // write channel-major y1[b][o][n] + stats
    #pragma unroll
    for (int j = 0; j < 8; j++) {
        int ol = (j < 4) ? ty * 4 + j : 64 + ty * 4 + j - 4;
        float* row = g_y1 + ((size_t)b * O1_ + ot * 128 + ol) * N1_ + nt * 128;
        *(float4*)&row[tx * 4]      = make_float4(acc[0][j], acc[1][j], acc[2][j], acc[3][j]);
        *(float4*)&row[tx * 4 + 64] = make_float4(acc[4][j], acc[5][j], acc[6][j], acc[7][j]);

        float s = 0.f, q = 0.f;
        #pragma unroll
        for (int i = 0; i < 8; i++) { s += acc[i][j]; q = fmaf(acc[i][j], acc[i][j], q); }
        #pragma unroll
        for (int off = 1; off < 16; off <<= 1) {
            s += __shfl_xor_sync(0xffffffffu, s, off);
            q += __shfl_xor_sync(0xffffffffu, q, off);
        }
        if (tx == 0) { atomicAdd(&red_s[ol], s); atomicAdd(&red_q[ol], q); }
    }
    __syncthreads();
    if (tid < 128) {
        atomicAdd(&g_s1[ot * 128 + tid], red_s[tid]);
        atomicAdd(&g_q1[ot * 128 + tid], red_q[tid]);
    }
}

__global__ void fin_stats1(const float* __restrict__ g, const float* __restrict__ be) {
    int c = threadIdx.x;
    if (c < O1_) {
        const float invN = 1.0f / (float)ROWS_TOT;
        float m = g_s1[c] * invN;
        float v = g_q1[c] * invN - m * m;
        float sc = g[c] * rsqrtf(v + 1e-5f);
        g_scale1[c] = sc;
        g_shift1[c] = be[c] - m * sc;
    }
}
__global__ void fin_stats2(const float* __restrict__ g, const float* __restrict__ be) {
    int c = threadIdx.x;
    if (c < O2_) {
        const float invN = 1.0f / (float)ROWS_TOT;
        float m = g_s2[c] * invN;
        float v = g_q2[c] * invN - m * m;
        float sc = g[c] * rsqrtf(v + 1e-5f);
        g_scale2[c] = sc;
        g_shift2[c] = be[c] - m * sc;
    }
}

// ---------------- 5) GEMM2 (BN1 affine+relu fused on A load) -----------------
// grid (N1/128, B), block 256
__global__ void __launch_bounds__(256) gemm2(const float* __restrict__ b2) {
    const int b = blockIdx.y, nt = blockIdx.x;
    __shared__ __align__(16) float As[16][128];
    __shared__ __align__(16) float Bs[16][128];
    __shared__ float ssc[O1_], ssh[O1_];
    __shared__ float red_s[128], red_q[128];
    const int tid = threadIdx.x, tx = tid & 15, ty = tid >> 4;
    float acc[8][8] = {};

    ssc[tid] = g_scale1[tid];
    ssh[tid] = g_shift1[tid];
    if (tid < 128) { red_s[tid] = 0.f; red_q[tid] = 0.f; }
    __syncthreads();

    const float* Ab = g_y1 + (size_t)b * O1_ * N1_ + nt * 128;

    for (int kc = 0; kc < O1_ / 16; kc++) {
        #pragma unroll
        for (int r = 0; r < 2; r++) {
            int e = tid + r * 256, row = e >> 5, c4 = (e & 31) * 4;
            int c = kc * 16 + row;
            float4 v = *(const float4*)&Ab[(size_t)c * N1_ + c4];
            float s = ssc[c], h = ssh[c];
            v.x = fmaxf(fmaf(s, v.x, h), 0.f);
            v.y = fmaxf(fmaf(s, v.y, h), 0.f);
            v.z = fmaxf(fmaf(s, v.z, h), 0.f);
            v.w = fmaxf(fmaf(s, v.w, h), 0.f);
            *(float4*)&As[row][c4] = v;
            *(float4*)&Bs[row][c4] = *(const float4*)&g_W2t[(size_t)c * O2_ + c4];
        }
        __syncthreads();
        #pragma unroll
        for (int k = 0; k < 16; k++) {
            float4 a0 = *(float4*)&As[k][tx * 4];
            float4 a1 = *(float4*)&As[k][tx * 4 + 64];
            float4 b0 = *(float4*)&Bs[k][ty * 4];
            float4 b1 = *(float4*)&Bs[k][ty * 4 + 64];
            float an[8] = {a0.x, a0.y, a0.z, a0.w, a1.x, a1.y, a1.z, a1.w};
            float ob[8] = {b0.x, b0.y, b0.z, b0.w, b1.x, b1.y, b1.z, b1.w};
            #pragma unroll
            for (int i = 0; i < 8; i++)
                #pragma unroll
                for (int j = 0; j < 8; j++) acc[i][j] = fmaf(an[i], ob[j], acc[i][j]);
        }
        __syncthreads();
    }

    #pragma unroll
    for (int j = 0; j < 8; j++) {
        int ol = (j < 4) ? ty * 4 + j : 64 + ty * 4 + j - 4;
        float bb = b2[ol];
        #pragma unroll
        for (int i = 0; i < 8; i++) acc[i][j] += bb;

        float* row = g_y2 + ((size_t)b * O2_ + ol) * N1_ + nt * 128;
        *(float4*)&row[tx * 4]      = make_float4(acc[0][j], acc[1][j], acc[2][j], acc[3][j]);
        *(float4*)&row[tx * 4 + 64] = make_float4(acc[4][j], acc[5][j], acc[6][j], acc[7][j]);

        float s = 0.f, q = 0.f;
        #pragma unroll
        for (int i = 0; i < 8; i++) { s += acc[i][j]; q = fmaf(acc[i][j], acc[i][j], q); }
        #pragma unroll
        for (int off = 1; off < 16; off <<= 1) {
            s += __shfl_xor_sync(0xffffffffu, s, off);
            q += __shfl_xor_sync(0xffffffffu, q, off);
        }
        if (tx == 0) { atomicAdd(&red_s[ol], s); atomicAdd(&red_q[ol], q); }
    }
    __syncthreads();
    if (tid < 128) {
        atomicAdd(&g_s2[tid], red_s[tid]);
        atomicAdd(&g_q2[tid], red_q[tid]);
    }
}

// ---------------- 6) finalize: BN2 affine + relu (already channel-major) ----
__global__ void finalize(float* __restrict__ out) {
    int idx = blockIdx.x * 256 + threadIdx.x;          // float4 index
    float4 v = ((const float4*)g_y2)[idx];
    int o = (idx / (N1_ / 4)) & (O2_ - 1);
    float s = g_scale2[o], h = g_shift2[o];
    v.x = fmaxf(fmaf(s, v.x, h), 0.f);
    v.y = fmaxf(fmaf(s, v.y, h), 0.f);
    v.z = fmaxf(fmaf(s, v.z, h), 0.f);
    v.w = fmaxf(fmaf(s, v.w, h), 0.f);
    ((float4*)out)[idx] = v;
}

// ---------------- launch ----------------------------------------------------
extern "C" void kernel_launch(void* const* d_in, const int* in_sizes, int n_in,
                              void* d_out, int out_size) {
    const float* xyz1 = (const float*)d_in[0];
    const float* xyz2 = (const float*)d_in[1];
    const float* p1   = (const float*)d_in[2];
    const float* p2   = (const float*)d_in[3];
    const float* W1   = (const float*)d_in[4];
    const float* b1   = (const float*)d_in[5];
    const float* g1   = (const float*)d_in[6];
    const float* be1  = (const float*)d_in[7];
    const float* W2   = (const float*)d_in[8];
    const float* b2   = (const float*)d_in[9];
    const float* g2   = (const float*)d_in[10];
    const float* be2  = (const float*)d_in[11];
    float* out = (float*)d_out;

    wtrans<<<384, 256>>>(W1, W2);
    knn_kernel<<<dim3(N1_ / 256, B_), 128>>>(xyz1, xyz2);
    zero_stats<<<1, 256>>>();
    zt_gemm<<<dim3(N2_ / 128, O1_ / 128, B_), 256>>>(p2);
    gemm1<<<dim3(N1_ / 128, O1_ / 128, B_), 256>>>(p1, b1);
    fin_stats1<<<1, O1_>>>(g1, be1);
    gemm2<<<dim3(N1_ / 128, B_), 256>>>(b2);
    fin_stats2<<<1, O2_>>>(g2, be2);
    finalize<<<(B_ * O2_ * N1_ / 4) / 256, 256>>>(out);
}

// round 4
// speedup vs baseline: 1.2945x; 1.2945x over previous
#include <cuda_runtime.h>
#include <math.h>
#include <stdint.h>

#define B_ 4
#define N1_ 16384
#define N2_ 4096
#define C1_ 128
#define C2_ 256
#define O1_ 256
#define O2_ 128
#define ROWS_TOT (B_ * N1_)

// ---------------- scratch ----------------------------------------------------
__device__ int   g_idx[B_ * N1_ * 3];
__device__ float g_w  [B_ * N1_ * 3];
__device__ float g_Zt [B_ * N2_ * O1_];          // [b][m][o]
__device__ float g_y1 [B_ * O1_ * N1_];          // [b][o][n]  channel-major
__device__ float g_y2 [B_ * O2_ * N1_];          // [b][o][n]
__device__ float g_s1[O1_], g_q1[O1_], g_scale1[O1_], g_shift1[O1_];
__device__ float g_s2[O2_], g_q2[O2_], g_scale2[O2_], g_shift2[O2_];

// ---------------- helpers ----------------------------------------------------
__device__ __forceinline__ float f2tf(float f) {
    uint32_t r;
    asm("cvt.rna.tf32.f32 %0, %1;" : "=r"(r) : "f"(f));
    return __uint_as_float(r);
}
__device__ __forceinline__ void mma8(float* c, const uint32_t* a, const uint32_t* b) {
    asm volatile(
        "mma.sync.aligned.m16n8k8.row.col.f32.tf32.tf32.f32 "
        "{%0,%1,%2,%3}, {%4,%5,%6,%7}, {%8,%9}, {%0,%1,%2,%3};"
        : "+f"(c[0]), "+f"(c[1]), "+f"(c[2]), "+f"(c[3])
        : "r"(a[0]), "r"(a[1]), "r"(a[2]), "r"(a[3]), "r"(b[0]), "r"(b[1]));
}

// ---------------- 1) 3-NN ----------------------------------------------------
__global__ void knn_kernel(const float* __restrict__ xyz1,
                           const float* __restrict__ xyz2) {
    const int b = blockIdx.y;
    const int tid = threadIdx.x;
    const int na = blockIdx.x * 256 + tid;
    const int nb = na + 128;
    __shared__ float4 sc[1024];

    const float* X1 = xyz1 + (size_t)b * 3 * N1_;
    const float* X2 = xyz2 + (size_t)b * 3 * N2_;
    const float ax = X1[na], ay = X1[N1_ + na], az = X1[2 * N1_ + na];
    const float bx = X1[nb], by = X1[N1_ + nb], bz = X1[2 * N1_ + nb];

    float A0 = 3.4e38f, A1 = 3.4e38f, A2 = 3.4e38f; int Ai0 = 0, Ai1 = 0, Ai2 = 0;
    float B0 = 3.4e38f, B1 = 3.4e38f, B2 = 3.4e38f; int Bi0 = 0, Bi1 = 0, Bi2 = 0;

    for (int t = 0; t < N2_ / 1024; t++) {
        __syncthreads();
        for (int j = tid; j < 1024; j += 128) {
            int gg = t * 1024 + j;
            sc[j] = make_float4(X2[gg], X2[N2_ + gg], X2[2 * N2_ + gg], 0.f);
        }
        __syncthreads();
        #pragma unroll 4
        for (int j = 0; j < 1024; j++) {
            float4 p = sc[j];
            int jj = t * 1024 + j;
            {
                float dx = ax - p.x, dy = ay - p.y, dz = az - p.z;
                float d = fmaf(dx, dx, fmaf(dy, dy, dz * dz));
                if (d < A2) {
                    if (d < A1) {
                        A2 = A1; Ai2 = Ai1;
                        if (d < A0) { A1 = A0; Ai1 = Ai0; A0 = d; Ai0 = jj; }
                        else        { A1 = d;  Ai1 = jj; }
                    } else { A2 = d; Ai2 = jj; }
                }
            }
            {
                float dx = bx - p.x, dy = by - p.y, dz = bz - p.z;
                float d = fmaf(dx, dx, fmaf(dy, dy, dz * dz));
                if (d < B2) {
                    if (d < B1) {
                        B2 = B1; Bi2 = Bi1;
                        if (d < B0) { B1 = B0; Bi1 = Bi0; B0 = d; Bi0 = jj; }
                        else        { B1 = d;  Bi1 = jj; }
                    } else { B2 = d; Bi2 = jj; }
                }
            }
        }
    }
    {
        float d0 = fmaxf(A0, 1e-10f), d1 = fmaxf(A1, 1e-10f), d2 = fmaxf(A2, 1e-10f);
        float w0 = 1.f / d0, w1 = 1.f / d1, w2 = 1.f / d2;
        float inv = 1.f / (w0 + w1 + w2);
        size_t base = ((size_t)b * N1_ + na) * 3;
        g_idx[base] = Ai0; g_idx[base + 1] = Ai1; g_idx[base + 2] = Ai2;
        g_w[base] = w0 * inv; g_w[base + 1] = w1 * inv; g_w[base + 2] = w2 * inv;
    }
    {
        float d0 = fmaxf(B0, 1e-10f), d1 = fmaxf(B1, 1e-10f), d2 = fmaxf(B2, 1e-10f);
        float w0 = 1.f / d0, w1 = 1.f / d1, w2 = 1.f / d2;
        float inv = 1.f / (w0 + w1 + w2);
        size_t base = ((size_t)b * N1_ + nb) * 3;
        g_idx[base] = Bi0; g_idx[base + 1] = Bi1; g_idx[base + 2] = Bi2;
        g_w[base] = w0 * inv; g_w[base + 1] = w1 * inv; g_w[base + 2] = w2 * inv;
    }
}

// ---------------- 2) zero stats ---------------------------------------------
__global__ void zero_stats() {
    int t = threadIdx.x;
    if (t < O1_) { g_s1[t] = 0.f; g_q1[t] = 0.f; }
    if (t < O2_) { g_s2[t] = 0.f; g_q2[t] = 0.f; }
}

// ---------------- unified tensor-core GEMM -----------------------------------
// D[o 128][n 128] = A[o][K] * X[K][n]  per (block, batch)
// MODE 0: zt   (A=W1+128, X=p2, out=g_Zt [m][o])
// MODE 1: gemm1(A=W1,     X=p1, out=g_y1, + bias + 3NN-gather + BN1 stats)
// MODE 2: gemm2(A=W2,     X=g_y1 w/ BN1-affine+relu, out=g_y2, + bias + BN2 stats)
template<int KTOT, int LDA, int NX, int MODE>
__global__ void __launch_bounds__(256) gemm_core(const float* __restrict__ Aw,
                                                 const float* __restrict__ Xin,
                                                 const float* __restrict__ bias) {
    const int b = blockIdx.z, bo = blockIdx.y, bn = blockIdx.x;
    const int tid = threadIdx.x, lane = tid & 31, wid = tid >> 5;
    const int wm = wid >> 2, wn = wid & 3;
    const int g = lane >> 2, tg = lane & 3;

    __shared__ union {
        struct { float As[128][20]; float Bs[16][136]; } mb;
        float Cs[128][68];
    } su;
    __shared__ int   sidx[128][3];
    __shared__ float sw[128][3];
    __shared__ float ssc[O1_], ssh[O1_];

    float acc[4][4][4] = {};

    if (MODE == 1 && tid < 128) {
        size_t base = ((size_t)b * N1_ + bn * 128 + tid) * 3;
        #pragma unroll
        for (int k = 0; k < 3; k++) { sidx[tid][k] = g_idx[base + k]; sw[tid][k] = g_w[base + k]; }
    }
    if (MODE == 2) { ssc[tid] = g_scale1[tid]; ssh[tid] = g_shift1[tid]; }
    __syncthreads();

    const float* Ab = Aw + (size_t)(bo * 128) * LDA;
    const float* Xb = (MODE == 2 ? (const float*)g_y1 : Xin) + (size_t)b * KTOT * NX + bn * 128;

    for (int kc = 0; kc < KTOT / 16; kc++) {
        // stage A tile [128 o][16 k], row-major from W
        #pragma unroll
        for (int r = 0; r < 2; r++) {
            int e = tid + r * 256;
            int row = e >> 2, q = (e & 3) * 4;
            float4 v = *(const float4*)&Ab[(size_t)row * LDA + kc * 16 + q];
            v.x = f2tf(v.x); v.y = f2tf(v.y); v.z = f2tf(v.z); v.w = f2tf(v.w);
            *(float4*)&su.mb.As[row][q] = v;
        }
        // stage B tile [16 k][128 n]
        #pragma unroll
        for (int r = 0; r < 2; r++) {
            int e = tid + r * 256;
            int row = e >> 5, q = (e & 31) * 4;
            int c = kc * 16 + row;
            float4 v = *(const float4*)&Xb[(size_t)c * NX + q];
            if (MODE == 2) {
                float s = ssc[c], hh = ssh[c];
                v.x = fmaxf(fmaf(s, v.x, hh), 0.f);
                v.y = fmaxf(fmaf(s, v.y, hh), 0.f);
                v.z = fmaxf(fmaf(s, v.z, hh), 0.f);
                v.w = fmaxf(fmaf(s, v.w, hh), 0.f);
            }
            v.x = f2tf(v.x); v.y = f2tf(v.y); v.z = f2tf(v.z); v.w = f2tf(v.w);
            *(float4*)&su.mb.Bs[row][q] = v;
        }
        __syncthreads();
        #pragma unroll
        for (int kk = 0; kk < 16; kk += 8) {
            uint32_t afr[4][4], bfr[4][2];
            #pragma unroll
            for (int mt = 0; mt < 4; mt++) {
                int row = wm * 64 + mt * 16 + g;
                afr[mt][0] = __float_as_uint(su.mb.As[row][kk + tg]);
                afr[mt][1] = __float_as_uint(su.mb.As[row + 8][kk + tg]);
                afr[mt][2] = __float_as_uint(su.mb.As[row][kk + tg + 4]);
                afr[mt][3] = __float_as_uint(su.mb.As[row + 8][kk + tg + 4]);
            }
            #pragma unroll
            for (int nt = 0; nt < 4; nt++) {
                int col = wn * 32 + nt * 8 + g;
                bfr[nt][0] = __float_as_uint(su.mb.Bs[kk + tg][col]);
                bfr[nt][1] = __float_as_uint(su.mb.Bs[kk + tg + 4][col]);
            }
            #pragma unroll
            for (int mt = 0; mt < 4; mt++)
                #pragma unroll
                for (int nt = 0; nt < 4; nt++)
                    mma8(acc[mt][nt], afr[mt], bfr[nt]);
        }
        __syncthreads();
    }

    // ---------------- epilogue: per o-half through smem Cs[n][o] ------------
    for (int h = 0; h < 2; h++) {
        if (wm == h) {
            #pragma unroll
            for (int mt = 0; mt < 4; mt++) {
                int o0 = mt * 16 + g;
                #pragma unroll
                for (int nt = 0; nt < 4; nt++) {
                    int n0 = wn * 32 + nt * 8 + 2 * tg;
                    su.Cs[n0][o0]          = acc[mt][nt][0];
                    su.Cs[n0 + 1][o0]      = acc[mt][nt][1];
                    su.Cs[n0][o0 + 8]      = acc[mt][nt][2];
                    su.Cs[n0 + 1][o0 + 8]  = acc[mt][nt][3];
                }
            }
        }
        __syncthreads();

        if (MODE == 1) {
            // 3-NN gather add: point-uniform per half-warp, lanes span o (coalesced)
            const float* Ztb = g_Zt + (size_t)b * N2_ * O1_ + bo * 128 + h * 64;
            int pbase = wid * 16;
            #pragma unroll
            for (int it = 0; it < 8; it++) {
                int p = pbase + it * 2 + (lane >> 4);
                int o4 = (lane & 15) * 4;
                float4 v = *(float4*)&su.Cs[p][o4];
                #pragma unroll
                for (int k3 = 0; k3 < 3; k3++) {
                    float wv = sw[p][k3];
                    float4 z = *(const float4*)&Ztb[(size_t)sidx[p][k3] * O1_ + o4];
                    v.x = fmaf(wv, z.x, v.x); v.y = fmaf(wv, z.y, v.y);
                    v.z = fmaf(wv, z.z, v.z); v.w = fmaf(wv, z.w, v.w);
                }
                *(float4*)&su.Cs[p][o4] = v;
            }
            __syncthreads();
        }

        if (MODE == 0) {
            // write Zt rows [point][o] (coalesced float4)
            int pbase = wid * 16;
            #pragma unroll
            for (int it = 0; it < 8; it++) {
                int p = pbase + it * 2 + (lane >> 4);
                int o4 = (lane & 15) * 4;
                float4 v = *(float4*)&su.Cs[p][o4];
                *(float4*)&g_Zt[((size_t)b * N2_ + bn * 128 + p) * O1_ + bo * 128 + h * 64 + o4] = v;
            }
        } else {
            // bias + stats + channel-major write: o-uniform per warp-iter, lanes span n
            const int OTOT = (MODE == 1) ? O1_ : O2_;
            float* Yb = (MODE == 1) ? g_y1 : g_y2;
            #pragma unroll
            for (int r = 0; r < 8; r++) {
                int o_loc = wid * 8 + r;
                int o = bo * 128 + h * 64 + o_loc;
                float bb = bias[o];
                float* yrow = Yb + ((size_t)b * OTOT + o) * N1_ + bn * 128;
                float s = 0.f, q = 0.f;
                #pragma unroll
                for (int itn = 0; itn < 4; itn++) {
                    int n = lane + itn * 32;
                    float v = su.Cs[n][o_loc] + bb;
                    s += v; q = fmaf(v, v, q);
                    yrow[n] = v;
                }
                #pragma unroll
                for (int off = 16; off > 0; off >>= 1) {
                    s += __shfl_xor_sync(0xffffffffu, s, off);
                    q += __shfl_xor_sync(0xffffffffu, q, off);
                }
                if (lane == 0) {
                    if (MODE == 1) { atomicAdd(&g_s1[o], s); atomicAdd(&g_q1[o], q); }
                    else           { atomicAdd(&g_s2[o], s); atomicAdd(&g_q2[o], q); }
                }
            }
        }
        __syncthreads();
    }
}

// ---------------- BN finalize -------------------------------------------------
__global__ void fin_stats1(const float* __restrict__ g, const float* __restrict__ be) {
    int c = threadIdx.x;
    if (c < O1_) {
        const float invN = 1.0f / (float)ROWS_TOT;
        float m = g_s1[c] * invN;
        float v = g_q1[c] * invN - m * m;
        float sc = g[c] * rsqrtf(v + 1e-5f);
        g_scale1[c] = sc;
        g_shift1[c] = be[c] - m * sc;
    }
}
__global__ void fin_stats2(const float* __restrict__ g, const float* __restrict__ be) {
    int c = threadIdx.x;
    if (c < O2_) {
        const float invN = 1.0f / (float)ROWS_TOT;
        float m = g_s2[c] * invN;
        float v = g_q2[c] * invN - m * m;
        float sc = g[c] * rsqrtf(v + 1e-5f);
        g_scale2[c] = sc;
        g_shift2[c] = be[c] - m * sc;
    }
}

// ---------------- finalize: BN2 affine + relu --------------------------------
__global__ void finalize(float* __restrict__ out) {
    int idx = blockIdx.x * 256 + threadIdx.x;          // float4 index
    float4 v = ((const float4*)g_y2)[idx];
    int o = (idx / (N1_ / 4)) & (O2_ - 1);
    float s = g_scale2[o], h = g_shift2[o];
    v.x = fmaxf(fmaf(s, v.x, h), 0.f);
    v.y = fmaxf(fmaf(s, v.y, h), 0.f);
    v.z = fmaxf(fmaf(s, v.z, h), 0.f);
    v.w = fmaxf(fmaf(s, v.w, h), 0.f);
    ((float4*)out)[idx] = v;
}

// ---------------- launch ------------------------------------------------------
extern "C" void kernel_launch(void* const* d_in, const int* in_sizes, int n_in,
                              void* d_out, int out_size) {
    const float* xyz1 = (const float*)d_in[0];
    const float* xyz2 = (const float*)d_in[1];
    const float* p1   = (const float*)d_in[2];
    const float* p2   = (const float*)d_in[3];
    const float* W1   = (const float*)d_in[4];
    const float* b1   = (const float*)d_in[5];
    const float* g1   = (const float*)d_in[6];
    const float* be1  = (const float*)d_in[7];
    const float* W2   = (const float*)d_in[8];
    const float* b2   = (const float*)d_in[9];
    const float* g2   = (const float*)d_in[10];
    const float* be2  = (const float*)d_in[11];
    float* out = (float*)d_out;

    knn_kernel<<<dim3(N1_ / 256, B_), 128>>>(xyz1, xyz2);
    zero_stats<<<1, 256>>>();
    // Zt = W1[:,128:384] . p2   (K=256)
    gemm_core<256, 384, N2_, 0><<<dim3(N2_ / 128, O1_ / 128, B_), 256>>>(W1 + 128, p2, nullptr);
    // y1 = W1[:,0:128] . p1 + b1 + gather(Zt)   (K=128)
    gemm_core<128, 384, N1_, 1><<<dim3(N1_ / 128, O1_ / 128, B_), 256>>>(W1, p1, b1);
    fin_stats1<<<1, O1_>>>(g1, be1);
    // y2 = W2 . relu(aff1(y1)) + b2   (K=256)
    gemm_core<256, 256, N1_, 2><<<dim3(N1_ / 128, 1, B_), 256>>>(W2, nullptr, b2);
    fin_stats2<<<1, O2_>>>(g2, be2);
    finalize<<<(B_ * O2_ * N1_ / 4) / 256, 256>>>(out);
}

// round 5
// speedup vs baseline: 1.3445x; 1.0387x over previous
#include <cuda_runtime.h>
#include <math.h>
#include <stdint.h>

#define B_ 4
#define N1_ 16384
#define N2_ 4096
#define C1_ 128
#define C2_ 256
#define O1_ 256
#define O2_ 128
#define ROWS_TOT (B_ * N1_)

// ---------------- scratch ----------------------------------------------------
__device__ int   g_idx[B_ * N1_ * 3];
__device__ float g_w  [B_ * N1_ * 3];
__device__ float g_Zt [B_ * N2_ * O1_];          // [b][m][o]
__device__ float g_y1 [B_ * O1_ * N1_];          // [b][o][n]  channel-major
__device__ float g_y2 [B_ * O2_ * N1_];          // [b][o][n]
__device__ float g_s1[O1_], g_q1[O1_], g_scale1[O1_], g_shift1[O1_];
__device__ float g_s2[O2_], g_q2[O2_], g_scale2[O2_], g_shift2[O2_];

// ---------------- helpers ----------------------------------------------------
__device__ __forceinline__ uint32_t f2tf_u(float f) {
    uint32_t r;
    asm("cvt.rna.tf32.f32 %0, %1;" : "=r"(r) : "f"(f));
    return r;
}
__device__ __forceinline__ void mma8(float* c, const uint32_t* a, const uint32_t* b) {
    asm volatile(
        "mma.sync.aligned.m16n8k8.row.col.f32.tf32.tf32.f32 "
        "{%0,%1,%2,%3}, {%4,%5,%6,%7}, {%8,%9}, {%0,%1,%2,%3};"
        : "+f"(c[0]), "+f"(c[1]), "+f"(c[2]), "+f"(c[3])
        : "r"(a[0]), "r"(a[1]), "r"(a[2]), "r"(a[3]), "r"(b[0]), "r"(b[1]));
}
__device__ __forceinline__ void cp16(uint32_t dst, const void* src) {
    asm volatile("cp.async.cg.shared.global [%0], [%1], 16;\n" :: "r"(dst), "l"(src));
}
__device__ __forceinline__ void cp_commit() {
    asm volatile("cp.async.commit_group;\n");
}
template<int N>
__device__ __forceinline__ void cp_wait() {
    asm volatile("cp.async.wait_group %0;\n" :: "n"(N));
}

// ---------------- 1) 3-NN ----------------------------------------------------
__global__ void knn_kernel(const float* __restrict__ xyz1,
                           const float* __restrict__ xyz2) {
    const int b = blockIdx.y;
    const int tid = threadIdx.x;
    const int na = blockIdx.x * 256 + tid;
    const int nb = na + 128;
    __shared__ float4 sc[1024];

    const float* X1 = xyz1 + (size_t)b * 3 * N1_;
    const float* X2 = xyz2 + (size_t)b * 3 * N2_;
    const float ax = X1[na], ay = X1[N1_ + na], az = X1[2 * N1_ + na];
    const float bx = X1[nb], by = X1[N1_ + nb], bz = X1[2 * N1_ + nb];

    float A0 = 3.4e38f, A1 = 3.4e38f, A2 = 3.4e38f; int Ai0 = 0, Ai1 = 0, Ai2 = 0;
    float B0 = 3.4e38f, B1 = 3.4e38f, B2 = 3.4e38f; int Bi0 = 0, Bi1 = 0, Bi2 = 0;

    for (int t = 0; t < N2_ / 1024; t++) {
        __syncthreads();
        for (int j = tid; j < 1024; j += 128) {
            int gg = t * 1024 + j;
            sc[j] = make_float4(X2[gg], X2[N2_ + gg], X2[2 * N2_ + gg], 0.f);
        }
        __syncthreads();
        #pragma unroll 4
        for (int j = 0; j < 1024; j++) {
            float4 p = sc[j];
            int jj = t * 1024 + j;
            {
                float dx = ax - p.x, dy = ay - p.y, dz = az - p.z;
                float d = fmaf(dx, dx, fmaf(dy, dy, dz * dz));
                if (d < A2) {
                    if (d < A1) {
                        A2 = A1; Ai2 = Ai1;
                        if (d < A0) { A1 = A0; Ai1 = Ai0; A0 = d; Ai0 = jj; }
                        else        { A1 = d;  Ai1 = jj; }
                    } else { A2 = d; Ai2 = jj; }
                }
            }
            {
                float dx = bx - p.x, dy = by - p.y, dz = bz - p.z;
                float d = fmaf(dx, dx, fmaf(dy, dy, dz * dz));
                if (d < B2) {
                    if (d < B1) {
                        B2 = B1; Bi2 = Bi1;
                        if (d < B0) { B1 = B0; Bi1 = Bi0; B0 = d; Bi0 = jj; }
                        else        { B1 = d;  Bi1 = jj; }
                    } else { B2 = d; Bi2 = jj; }
                }
            }
        }
    }
    {
        float d0 = fmaxf(A0, 1e-10f), d1 = fmaxf(A1, 1e-10f), d2 = fmaxf(A2, 1e-10f);
        float w0 = 1.f / d0, w1 = 1.f / d1, w2 = 1.f / d2;
        float inv = 1.f / (w0 + w1 + w2);
        size_t base = ((size_t)b * N1_ + na) * 3;
        g_idx[base] = Ai0; g_idx[base + 1] = Ai1; g_idx[base + 2] = Ai2;
        g_w[base] = w0 * inv; g_w[base + 1] = w1 * inv; g_w[base + 2] = w2 * inv;
    }
    {
        float d0 = fmaxf(B0, 1e-10f), d1 = fmaxf(B1, 1e-10f), d2 = fmaxf(B2, 1e-10f);
        float w0 = 1.f / d0, w1 = 1.f / d1, w2 = 1.f / d2;
        float inv = 1.f / (w0 + w1 + w2);
        size_t base = ((size_t)b * N1_ + nb) * 3;
        g_idx[base] = Bi0; g_idx[base + 1] = Bi1; g_idx[base + 2] = Bi2;
        g_w[base] = w0 * inv; g_w[base + 1] = w1 * inv; g_w[base + 2] = w2 * inv;
    }
}

// ---------------- 2) zero stats ---------------------------------------------
__global__ void zero_stats() {
    int t = threadIdx.x;
    if (t < O1_) { g_s1[t] = 0.f; g_q1[t] = 0.f; }
    if (t < O2_) { g_s2[t] = 0.f; g_q2[t] = 0.f; }
}

// ---------------- unified tensor-core GEMM, cp.async double-buffered ---------
// D[o 128][n 128] = A[o][K] * X[K][n]  per (block, batch)
// MODE 0: zt, MODE 1: gemm1(+gather+BN1 stats), MODE 2: gemm2(BN1 affine on B)
template<int KTOT, int LDA, int NX, int MODE>
__global__ void __launch_bounds__(256) gemm_core(const float* __restrict__ Aw,
                                                 const float* __restrict__ Xin,
                                                 const float* __restrict__ bias) {
    const int b = blockIdx.z, bo = blockIdx.y, bn = blockIdx.x;
    const int tid = threadIdx.x, lane = tid & 31, wid = tid >> 5;
    const int wm = wid >> 2, wn = wid & 3;
    const int g = lane >> 2, tg = lane & 3;
    const int KT16 = KTOT / 16;

    __shared__ union {
        struct { float As[2][128][20]; float Bs[2][16][136]; } mb;
        float Cs[128][68];
    } su;
    __shared__ int   sidx[128][3];
    __shared__ float sw[128][3];
    __shared__ float ssc[O1_], ssh[O1_];

    float acc[4][4][4] = {};

    if (MODE == 1 && tid < 128) {
        size_t base = ((size_t)b * N1_ + bn * 128 + tid) * 3;
        #pragma unroll
        for (int k = 0; k < 3; k++) { sidx[tid][k] = g_idx[base + k]; sw[tid][k] = g_w[base + k]; }
    }
    if (MODE == 2) { ssc[tid] = g_scale1[tid]; ssh[tid] = g_shift1[tid]; }

    const float* Ab = Aw + (size_t)(bo * 128) * LDA;
    const float* Xb = (MODE == 2 ? (const float*)g_y1 : Xin) + (size_t)b * KTOT * NX + bn * 128;

    // staging lambda-equivalent: issue cp.async for k-chunk kc into stage s
    const int a_row = tid >> 1, a_q = (tid & 1) * 8;            // 2 chunks/thread -> rows, 8-float cols
    const int b_row = tid >> 4, b_q = (tid & 15) * 8;           // 2 chunks/thread

    #define STAGE_TILE(s, kc)                                                            \
        do {                                                                             \
            uint32_t da = (uint32_t)__cvta_generic_to_shared(&su.mb.As[s][a_row][a_q]);  \
            const float* sa = &Ab[(size_t)a_row * LDA + (kc) * 16 + a_q];                \
            cp16(da, sa); cp16(da + 16, sa + 4);                                         \
            uint32_t db = (uint32_t)__cvta_generic_to_shared(&su.mb.Bs[s][b_row][b_q]);  \
            const float* sb = &Xb[(size_t)((kc) * 16 + b_row) * NX + b_q];               \
            cp16(db, sb); cp16(db + 16, sb + 4);                                         \
        } while (0)

    STAGE_TILE(0, 0);
    cp_commit();

    for (int kc = 0; kc < KT16; kc++) {
        cp_wait<0>();
        __syncthreads();
        if (kc + 1 < KT16) {
            STAGE_TILE((kc + 1) & 1, kc + 1);
            cp_commit();
        }
        const int s = kc & 1;
        #pragma unroll
        for (int kk = 0; kk < 16; kk += 8) {
            uint32_t afr[4][4], bfr[4][2];
            #pragma unroll
            for (int mt = 0; mt < 4; mt++) {
                int row = wm * 64 + mt * 16 + g;
                afr[mt][0] = f2tf_u(su.mb.As[s][row][kk + tg]);
                afr[mt][1] = f2tf_u(su.mb.As[s][row + 8][kk + tg]);
                afr[mt][2] = f2tf_u(su.mb.As[s][row][kk + tg + 4]);
                afr[mt][3] = f2tf_u(su.mb.As[s][row + 8][kk + tg + 4]);
            }
            float s0 = 1.f, h0 = 0.f, s1 = 1.f, h1 = 0.f;
            if (MODE == 2) {
                int c0 = kc * 16 + kk + tg;
                s0 = ssc[c0]; h0 = ssh[c0];
                s1 = ssc[c0 + 4]; h1 = ssh[c0 + 4];
            }
            #pragma unroll
            for (int nt = 0; nt < 4; nt++) {
                int col = wn * 32 + nt * 8 + g;
                float v0 = su.mb.Bs[s][kk + tg][col];
                float v1 = su.mb.Bs[s][kk + tg + 4][col];
                if (MODE == 2) {
                    v0 = fmaxf(fmaf(s0, v0, h0), 0.f);
                    v1 = fmaxf(fmaf(s1, v1, h1), 0.f);
                }
                bfr[nt][0] = f2tf_u(v0);
                bfr[nt][1] = f2tf_u(v1);
            }
            #pragma unroll
            for (int mt = 0; mt < 4; mt++)
                #pragma unroll
                for (int nt = 0; nt < 4; nt++)
                    mma8(acc[mt][nt], afr[mt], bfr[nt]);
        }
    }
    __syncthreads();   // all fragment consumption done before Cs aliasing writes

    // ---------------- epilogue: per o-half through smem Cs[n][o] ------------
    for (int h = 0; h < 2; h++) {
        if (wm == h) {
            #pragma unroll
            for (int mt = 0; mt < 4; mt++) {
                int o0 = mt * 16 + g;
                #pragma unroll
                for (int nt = 0; nt < 4; nt++) {
                    int n0 = wn * 32 + nt * 8 + 2 * tg;
                    su.Cs[n0][o0]          = acc[mt][nt][0];
                    su.Cs[n0 + 1][o0]      = acc[mt][nt][1];
                    su.Cs[n0][o0 + 8]      = acc[mt][nt][2];
                    su.Cs[n0 + 1][o0 + 8]  = acc[mt][nt][3];
                }
            }
        }
        __syncthreads();

        if (MODE == 1) {
            const float* Ztb = g_Zt + (size_t)b * N2_ * O1_ + bo * 128 + h * 64;
            int pbase = wid * 16;
            #pragma unroll
            for (int it = 0; it < 8; it++) {
                int p = pbase + it * 2 + (lane >> 4);
                int o4 = (lane & 15) * 4;
                float4 v = *(float4*)&su.Cs[p][o4];
                #pragma unroll
                for (int k3 = 0; k3 < 3; k3++) {
                    float wv = sw[p][k3];
                    float4 z = *(const float4*)&Ztb[(size_t)sidx[p][k3] * O1_ + o4];
                    v.x = fmaf(wv, z.x, v.x); v.y = fmaf(wv, z.y, v.y);
                    v.z = fmaf(wv, z.z, v.z); v.w = fmaf(wv, z.w, v.w);
                }
                *(float4*)&su.Cs[p][o4] = v;
            }
            __syncthreads();
        }

        if (MODE == 0) {
            int pbase = wid * 16;
            #pragma unroll
            for (int it = 0; it < 8; it++) {
                int p = pbase + it * 2 + (lane >> 4);
                int o4 = (lane & 15) * 4;
                float4 v = *(float4*)&su.Cs[p][o4];
                *(float4*)&g_Zt[((size_t)b * N2_ + bn * 128 + p) * O1_ + bo * 128 + h * 64 + o4] = v;
            }
        } else {
            const int OTOT = (MODE == 1) ? O1_ : O2_;
            float* Yb = (MODE == 1) ? g_y1 : g_y2;
            #pragma unroll
            for (int r = 0; r < 8; r++) {
                int o_loc = wid * 8 + r;
                int o = bo * 128 + h * 64 + o_loc;
                float bb = bias[o];
                float* yrow = Yb + ((size_t)b * OTOT + o) * N1_ + bn * 128;
                float s = 0.f, q = 0.f;
                #pragma unroll
                for (int itn = 0; itn < 4; itn++) {
                    int n = lane + itn * 32;
                    float v = su.Cs[n][o_loc] + bb;
                    s += v; q = fmaf(v, v, q);
                    yrow[n] = v;
                }
                #pragma unroll
                for (int off = 16; off > 0; off >>= 1) {
                    s += __shfl_xor_sync(0xffffffffu, s, off);
                    q += __shfl_xor_sync(0xffffffffu, q, off);
                }
                if (lane == 0) {
                    if (MODE == 1) { atomicAdd(&g_s1[o], s); atomicAdd(&g_q1[o], q); }
                    else           { atomicAdd(&g_s2[o], s); atomicAdd(&g_q2[o], q); }
                }
            }
        }
        __syncthreads();
    }
    #undef STAGE_TILE
}

// ---------------- BN finalize -------------------------------------------------
__global__ void fin_stats1(const float* __restrict__ g, const float* __restrict__ be) {
    int c = threadIdx.x;
    if (c < O1_) {
        const float invN = 1.0f / (float)ROWS_TOT;
        float m = g_s1[c] * invN;
        float v = g_q1[c] * invN - m * m;
        float sc = g[c] * rsqrtf(v + 1e-5f);
        g_scale1[c] = sc;
        g_shift1[c] = be[c] - m * sc;
    }
}
__global__ void fin_stats2(const float* __restrict__ g, const float* __restrict__ be) {
    int c = threadIdx.x;
    if (c < O2_) {
        const float invN = 1.0f / (float)ROWS_TOT;
        float m = g_s2[c] * invN;
        float v = g_q2[c] * invN - m * m;
        float sc = g[c] * rsqrtf(v + 1e-5f);
        g_scale2[c] = sc;
        g_shift2[c] = be[c] - m * sc;
    }
}

// ---------------- finalize: BN2 affine + relu --------------------------------
__global__ void finalize(float* __restrict__ out) {
    int idx = blockIdx.x * 256 + threadIdx.x;          // float4 index
    float4 v = ((const float4*)g_y2)[idx];
    int o = (idx / (N1_ / 4)) & (O2_ - 1);
    float s = g_scale2[o], h = g_shift2[o];
    v.x = fmaxf(fmaf(s, v.x, h), 0.f);
    v.y = fmaxf(fmaf(s, v.y, h), 0.f);
    v.z = fmaxf(fmaf(s, v.z, h), 0.f);
    v.w = fmaxf(fmaf(s, v.w, h), 0.f);
    ((float4*)out)[idx] = v;
}

// ---------------- launch ------------------------------------------------------
extern "C" void kernel_launch(void* const* d_in, const int* in_sizes, int n_in,
                              void* d_out, int out_size) {
    const float* xyz1 = (const float*)d_in[0];
    const float* xyz2 = (const float*)d_in[1];
    const float* p1   = (const float*)d_in[2];
    const float* p2   = (const float*)d_in[3];
    const float* W1   = (const float*)d_in[4];
    const float* b1   = (const float*)d_in[5];
    const float* g1   = (const float*)d_in[6];
    const float* be1  = (const float*)d_in[7];
    const float* W2   = (const float*)d_in[8];
    const float* b2   = (const float*)d_in[9];
    const float* g2   = (const float*)d_in[10];
    const float* be2  = (const float*)d_in[11];
    float* out = (float*)d_out;

    knn_kernel<<<dim3(N1_ / 256, B_), 128>>>(xyz1, xyz2);
    zero_stats<<<1, 256>>>();
    gemm_core<256, 384, N2_, 0><<<dim3(N2_ / 128, O1_ / 128, B_), 256>>>(W1 + 128, p2, nullptr);
    gemm_core<128, 384, N1_, 1><<<dim3(N1_ / 128, O1_ / 128, B_), 256>>>(W1, p1, b1);
    fin_stats1<<<1, O1_>>>(g1, be1);
    gemm_core<256, 256, N1_, 2><<<dim3(N1_ / 128, 1, B_), 256>>>(W2, nullptr, b2);
    fin_stats2<<<1, O2_>>>(g2, be2);
    finalize<<<(B_ * O2_ * N1_ / 4) / 256, 256>>>(out);
}

// round 10
// speedup vs baseline: 1.3449x; 1.0003x over previous
#include <cuda_runtime.h>
#include <math.h>
#include <stdint.h>

#define B_ 4
#define N1_ 16384
#define N2_ 4096
#define C1_ 128
#define C2_ 256
#define O1_ 256
#define O2_ 128
#define ROWS_TOT (B_ * N1_)

// ---------------- scratch ----------------------------------------------------
__device__ int   g_idx[B_ * N1_ * 3];
__device__ float g_w  [B_ * N1_ * 3];
__device__ float g_W1c[O1_ * 384];               // tf32-rounded W1
__device__ float g_W2c[O2_ * O1_];               // tf32-rounded W2
__device__ float g_Zt [B_ * N2_ * O1_];          // [b][m][o]
__device__ float g_y1 [B_ * O1_ * N1_];          // [b][o][n]
__device__ float g_y2 [B_ * O2_ * N1_];          // [b][o][n]
__device__ float g_s1[O1_], g_q1[O1_], g_scale1[O1_], g_shift1[O1_];
__device__ float g_s2[O2_], g_q2[O2_], g_scale2[O2_], g_shift2[O2_];

// ---------------- helpers ----------------------------------------------------
__device__ __forceinline__ uint32_t f2tf_u(float f) {
    uint32_t r;
    asm("cvt.rna.tf32.f32 %0, %1;" : "=r"(r) : "f"(f));
    return r;
}
__device__ __forceinline__ void mma8(float* c, const uint32_t* a, const uint32_t* b) {
    asm volatile(
        "mma.sync.aligned.m16n8k8.row.col.f32.tf32.tf32.f32 "
        "{%0,%1,%2,%3}, {%4,%5,%6,%7}, {%8,%9}, {%0,%1,%2,%3};"
        : "+f"(c[0]), "+f"(c[1]), "+f"(c[2]), "+f"(c[3])
        : "r"(a[0]), "r"(a[1]), "r"(a[2]), "r"(a[3]), "r"(b[0]), "r"(b[1]));
}
__device__ __forceinline__ void cp16(uint32_t dst, const void* src) {
    asm volatile("cp.async.cg.shared.global [%0], [%1], 16;\n" :: "r"(dst), "l"(src));
}
__device__ __forceinline__ void cp_commit() {
    asm volatile("cp.async.commit_group;\n");
}
template<int N>
__device__ __forceinline__ void cp_wait() {
    asm volatile("cp.async.wait_group %0;\n" :: "n"(N));
}

// ---------------- 0) weight tf32 pre-convert ---------------------------------
__global__ void wconv(const float* __restrict__ W1, const float* __restrict__ W2) {
    int i = blockIdx.x * 256 + threadIdx.x;
    if (i < O1_ * 384) g_W1c[i] = __uint_as_float(f2tf_u(W1[i]));
    if (i < O2_ * O1_) g_W2c[i] = __uint_as_float(f2tf_u(W2[i]));
}

// ---------------- 1) 3-NN: select on d' = |p|^2 - 2 q.p, fully scalar --------
__device__ __forceinline__ float dist3(const float* __restrict__ X2,
                                       float qx, float qy, float qz, int i) {
    float dx = qx - X2[i];
    float dy = qy - X2[N2_ + i];
    float dz = qz - X2[2 * N2_ + i];
    return fmaxf(fmaf(dx, dx, fmaf(dy, dy, dz * dz)), 1e-10f);
}

__global__ void knn_kernel(const float* __restrict__ xyz1,
                           const float* __restrict__ xyz2) {
    const int b = blockIdx.y;
    const int tid = threadIdx.x;
    const int na = blockIdx.x * 256 + tid;
    const int nb = na + 128;
    __shared__ float4 sc[1024];

    const float* X1 = xyz1 + (size_t)b * 3 * N1_;
    const float* X2 = xyz2 + (size_t)b * 3 * N2_;
    const float ax = X1[na], ay = X1[N1_ + na], az = X1[2 * N1_ + na];
    const float bx = X1[nb], by = X1[N1_ + nb], bz = X1[2 * N1_ + nb];
    const float ax2 = -2.f * ax, ay2 = -2.f * ay, az2 = -2.f * az;
    const float bx2 = -2.f * bx, by2 = -2.f * by, bz2 = -2.f * bz;

    float A0 = 3.4e38f, A1 = 3.4e38f, A2 = 3.4e38f; int Ai0 = 0, Ai1 = 0, Ai2 = 0;
    float B0 = 3.4e38f, B1 = 3.4e38f, B2 = 3.4e38f; int Bi0 = 0, Bi1 = 0, Bi2 = 0;

    for (int t = 0; t < N2_ / 1024; t++) {
        __syncthreads();
        for (int j = tid; j < 1024; j += 128) {
            int gg = t * 1024 + j;
            float px = X2[gg], py = X2[N2_ + gg], pz = X2[2 * N2_ + gg];
            sc[j] = make_float4(px, py, pz, fmaf(px, px, fmaf(py, py, pz * pz)));
        }
        __syncthreads();
        #pragma unroll 4
        for (int j = 0; j < 1024; j++) {
            float4 p = sc[j];
            int jj = t * 1024 + j;
            {
                float d = fmaf(ax2, p.x, fmaf(ay2, p.y, fmaf(az2, p.z, p.w)));
                if (d < A2) {
                    if (d < A1) {
                        A2 = A1; Ai2 = Ai1;
                        if (d < A0) { A1 = A0; Ai1 = Ai0; A0 = d; Ai0 = jj; }
                        else        { A1 = d;  Ai1 = jj; }
                    } else { A2 = d; Ai2 = jj; }
                }
            }
            {
                float d = fmaf(bx2, p.x, fmaf(by2, p.y, fmaf(bz2, p.z, p.w)));
                if (d < B2) {
                    if (d < B1) {
                        B2 = B1; Bi2 = Bi1;
                        if (d < B0) { B1 = B0; Bi1 = Bi0; B0 = d; Bi0 = jj; }
                        else        { B1 = d;  Bi1 = jj; }
                    } else { B2 = d; Bi2 = jj; }
                }
            }
        }
    }
    // exact-distance recompute for winners (matches reference); all scalar
    {
        float d0 = dist3(X2, ax, ay, az, Ai0);
        float d1 = dist3(X2, ax, ay, az, Ai1);
        float d2 = dist3(X2, ax, ay, az, Ai2);
        float w0 = 1.f / d0, w1 = 1.f / d1, w2 = 1.f / d2;
        float inv = 1.f / (w0 + w1 + w2);
        size_t base = ((size_t)b * N1_ + na) * 3;
        g_idx[base] = Ai0; g_idx[base + 1] = Ai1; g_idx[base + 2] = Ai2;
        g_w[base] = w0 * inv; g_w[base + 1] = w1 * inv; g_w[base + 2] = w2 * inv;
    }
    {
        float d0 = dist3(X2, bx, by, bz, Bi0);
        float d1 = dist3(X2, bx, by, bz, Bi1);
        float d2 = dist3(X2, bx, by, bz, Bi2);
        float w0 = 1.f / d0, w1 = 1.f / d1, w2 = 1.f / d2;
        float inv = 1.f / (w0 + w1 + w2);
        size_t base = ((size_t)b * N1_ + nb) * 3;
        g_idx[base] = Bi0; g_idx[base + 1] = Bi1; g_idx[base + 2] = Bi2;
        g_w[base] = w0 * inv; g_w[base + 1] = w1 * inv; g_w[base + 2] = w2 * inv;
    }
}

// ---------------- 2) zero stats ---------------------------------------------
__global__ void zero_stats() {
    int t = threadIdx.x;
    if (t < O1_) { g_s1[t] = 0.f; g_q1[t] = 0.f; }
    if (t < O2_) { g_s2[t] = 0.f; g_q2[t] = 0.f; }
}

// ---------------- unified tensor-core GEMM, 2-stage cp.async -----------------
// Weight matrix selected IN DEVICE CODE by MODE (device symbols must not be
// passed from host). MODE 0: zt, MODE 1: gemm1(+gather+BN1 stats),
// MODE 2: gemm2(BN1 affine on B).
template<int KTOT, int LDA, int NX, int MODE>
__global__ void __launch_bounds__(256) gemm_core(const float* __restrict__ Xin,
                                                 const float* __restrict__ bias) {
    const int b = blockIdx.z, bo = blockIdx.y, bn = blockIdx.x;
    const int tid = threadIdx.x, lane = tid & 31, wid = tid >> 5;
    const int wm = wid >> 2, wn = wid & 3;
    const int g = lane >> 2, tg = lane & 3;
    const int KT16 = KTOT / 16;

    __shared__ union {
        struct { float As[2][128][20]; float Bs[2][16][136]; } mb;
        float Cs[128][68];
    } su;
    __shared__ int   sidx[128][3];
    __shared__ float sw[128][3];
    __shared__ float ssc[O1_], ssh[O1_];

    float acc[4][4][4] = {};

    if (MODE == 1 && tid < 128) {
        size_t base = ((size_t)b * N1_ + bn * 128 + tid) * 3;
        #pragma unroll
        for (int k = 0; k < 3; k++) { sidx[tid][k] = g_idx[base + k]; sw[tid][k] = g_w[base + k]; }
    }
    if (MODE == 2) { ssc[tid] = g_scale1[tid]; ssh[tid] = g_shift1[tid]; }

    // device-side weight symbol selection (legal; host must not pass symbols)
    const float* Aw = (MODE == 0) ? (g_W1c + 128) : ((MODE == 1) ? g_W1c : g_W2c);
    const float* Ab = Aw + (size_t)(bo * 128) * LDA;
    const float* Xb = (MODE == 2 ? (const float*)g_y1 : Xin) + (size_t)b * KTOT * NX + bn * 128;

    const int a_row = tid >> 1, a_q = (tid & 1) * 8;
    const int b_row = tid >> 4, b_q = (tid & 15) * 8;

    #define STAGE_TILE(s, kc)                                                           \
        do {                                                                            \
            uint32_t da = (uint32_t)__cvta_generic_to_shared(&su.mb.As[s][a_row][a_q]); \
            const float* sa = &Ab[(size_t)a_row * LDA + (kc) * 16 + a_q];               \
            cp16(da, sa); cp16(da + 16, sa + 4);                                        \
            uint32_t db = (uint32_t)__cvta_generic_to_shared(&su.mb.Bs[s][b_row][b_q]); \
            const float* sb = &Xb[(size_t)((kc) * 16 + b_row) * NX + b_q];              \
            cp16(db, sb); cp16(db + 16, sb + 4);                                        \
        } while (0)

    STAGE_TILE(0, 0);
    cp_commit();

    for (int kc = 0; kc < KT16; kc++) {
        cp_wait<0>();
        __syncthreads();
        if (kc + 1 < KT16) {
            STAGE_TILE((kc + 1) & 1, kc + 1);
            cp_commit();
        }
        const int s = kc & 1;
        #pragma unroll
        for (int kk = 0; kk < 16; kk += 8) {
            uint32_t afr[4][4], bfr[4][2];
            #pragma unroll
            for (int mt = 0; mt < 4; mt++) {
                int row = wm * 64 + mt * 16 + g;
                afr[mt][0] = __float_as_uint(su.mb.As[s][row][kk + tg]);
                afr[mt][1] = __float_as_uint(su.mb.As[s][row + 8][kk + tg]);
                afr[mt][2] = __float_as_uint(su.mb.As[s][row][kk + tg + 4]);
                afr[mt][3] = __float_as_uint(su.mb.As[s][row + 8][kk + tg + 4]);
            }
            float s0 = 1.f, h0 = 0.f, s1 = 1.f, h1 = 0.f;
            if (MODE == 2) {
                int c0 = kc * 16 + kk + tg;
                s0 = ssc[c0]; h0 = ssh[c0];
                s1 = ssc[c0 + 4]; h1 = ssh[c0 + 4];
            }
            #pragma unroll
            for (int nt = 0; nt < 4; nt++) {
                int col = wn * 32 + nt * 8 + g;
                float v0 = su.mb.Bs[s][kk + tg][col];
                float v1 = su.mb.Bs[s][kk + tg + 4][col];
                if (MODE == 2) {
                    v0 = fmaxf(fmaf(s0, v0, h0), 0.f);
                    v1 = fmaxf(fmaf(s1, v1, h1), 0.f);
                }
                bfr[nt][0] = f2tf_u(v0);
                bfr[nt][1] = f2tf_u(v1);
            }
            #pragma unroll
            for (int mt = 0; mt < 4; mt++)
                #pragma unroll
                for (int nt = 0; nt < 4; nt++)
                    mma8(acc[mt][nt], afr[mt], bfr[nt]);
        }
    }
    __syncthreads();   // all fragment consumption done before Cs aliasing writes

    // ---------------- epilogue: per o-half through smem Cs[n][o] ------------
    for (int h = 0; h < 2; h++) {
        if (wm == h) {
            #pragma unroll
            for (int mt = 0; mt < 4; mt++) {
                int o0 = mt * 16 + g;
                #pragma unroll
                for (int nt = 0; nt < 4; nt++) {
                    int n0 = wn * 32 + nt * 8 + 2 * tg;
                    su.Cs[n0][o0]          = acc[mt][nt][0];
                    su.Cs[n0 + 1][o0]      = acc[mt][nt][1];
                    su.Cs[n0][o0 + 8]      = acc[mt][nt][2];
                    su.Cs[n0 + 1][o0 + 8]  = acc[mt][nt][3];
                }
            }
        }
        __syncthreads();

        if (MODE == 1) {
            const float* Ztb = g_Zt + (size_t)b * N2_ * O1_ + bo * 128 + h * 64;
            int pbase = wid * 16;
            #pragma unroll
            for (int it = 0; it < 8; it++) {
                int p = pbase + it * 2 + (lane >> 4);
                int o4 = (lane & 15) * 4;
                float4 v = *(float4*)&su.Cs[p][o4];
                #pragma unroll
                for (int k3 = 0; k3 < 3; k3++) {
                    float wv = sw[p][k3];
                    float4 z = *(const float4*)&Ztb[(size_t)sidx[p][k3] * O1_ + o4];
                    v.x = fmaf(wv, z.x, v.x); v.y = fmaf(wv, z.y, v.y);
                    v.z = fmaf(wv, z.z, v.z); v.w = fmaf(wv, z.w, v.w);
                }
                *(float4*)&su.Cs[p][o4] = v;
            }
            __syncthreads();
        }

        if (MODE == 0) {
            int pbase = wid * 16;
            #pragma unroll
            for (int it = 0; it < 8; it++) {
                int p = pbase + it * 2 + (lane >> 4);
                int o4 = (lane & 15) * 4;
                float4 v = *(float4*)&su.Cs[p][o4];
                *(float4*)&g_Zt[((size_t)b * N2_ + bn * 128 + p) * O1_ + bo * 128 + h * 64 + o4] = v;
            }
        } else {
            const int OTOT = (MODE == 1) ? O1_ : O2_;
            float* Yb = (MODE == 1) ? g_y1 : g_y2;
            #pragma unroll
            for (int r = 0; r < 8; r++) {
                int o_loc = wid * 8 + r;
                int o = bo * 128 + h * 64 + o_loc;
                float bb = bias[o];
                float* yrow = Yb + ((size_t)b * OTOT + o) * N1_ + bn * 128;
                float sv = 0.f, q = 0.f;
                #pragma unroll
                for (int itn = 0; itn < 4; itn++) {
                    int n = lane + itn * 32;
                    float v = su.Cs[n][o_loc] + bb;
                    sv += v; q = fmaf(v, v, q);
                    yrow[n] = v;
                }
                #pragma unroll
                for (int off = 16; off > 0; off >>= 1) {
                    sv += __shfl_xor_sync(0xffffffffu, sv, off);
                    q  += __shfl_xor_sync(0xffffffffu, q, off);
                }
                if (lane == 0) {
                    if (MODE == 1) { atomicAdd(&g_s1[o], sv); atomicAdd(&g_q1[o], q); }
                    else           { atomicAdd(&g_s2[o], sv); atomicAdd(&g_q2[o], q); }
                }
            }
        }
        __syncthreads();
    }
    #undef STAGE_TILE
}

// ---------------- BN finalize -------------------------------------------------
__global__ void fin_stats1(const float* __restrict__ g, const float* __restrict__ be) {
    int c = threadIdx.x;
    if (c < O1_) {
        const float invN = 1.0f / (float)ROWS_TOT;
        float m = g_s1[c] * invN;
        float v = g_q1[c] * invN - m * m;
        float sc = g[c] * rsqrtf(v + 1e-5f);
        g_scale1[c] = sc;
        g_shift1[c] = be[c] - m * sc;
    }
}
__global__ void fin_stats2(const float* __restrict__ g, const float* __restrict__ be) {
    int c = threadIdx.x;
    if (c < O2_) {
        const float invN = 1.0f / (float)ROWS_TOT;
        float m = g_s2[c] * invN;
        float v = g_q2[c] * invN - m * m;
        float sc = g[c] * rsqrtf(v + 1e-5f);
        g_scale2[c] = sc;
        g_shift2[c] = be[c] - m * sc;
    }
}

// ---------------- finalize: BN2 affine + relu --------------------------------
__global__ void finalize(float* __restrict__ out) {
    int idx = blockIdx.x * 256 + threadIdx.x;
    float4 v = ((const float4*)g_y2)[idx];
    int o = (idx / (N1_ / 4)) & (O2_ - 1);
    float s = g_scale2[o], h = g_shift2[o];
    v.x = fmaxf(fmaf(s, v.x, h), 0.f);
    v.y = fmaxf(fmaf(s, v.y, h), 0.f);
    v.z = fmaxf(fmaf(s, v.z, h), 0.f);
    v.w = fmaxf(fmaf(s, v.w, h), 0.f);
    ((float4*)out)[idx] = v;
}

// ---------------- launch ------------------------------------------------------
extern "C" void kernel_launch(void* const* d_in, const int* in_sizes, int n_in,
                              void* d_out, int out_size) {
    const float* xyz1 = (const float*)d_in[0];
    const float* xyz2 = (const float*)d_in[1];
    const float* p1   = (const float*)d_in[2];
    const float* p2   = (const float*)d_in[3];
    const float* W1   = (const float*)d_in[4];
    const float* b1   = (const float*)d_in[5];
    const float* g1   = (const float*)d_in[6];
    const float* be1  = (const float*)d_in[7];
    const float* W2   = (const float*)d_in[8];
    const float* b2   = (const float*)d_in[9];
    const float* g2   = (const float*)d_in[10];
    const float* be2  = (const float*)d_in[11];
    float* out = (float*)d_out;

    wconv<<<384, 256>>>(W1, W2);
    knn_kernel<<<dim3(N1_ / 256, B_), 128>>>(xyz1, xyz2);
    zero_stats<<<1, 256>>>();
    gemm_core<256, 384, N2_, 0><<<dim3(N2_ / 128, O1_ / 128, B_), 256>>>(p2, b1);
    gemm_core<128, 384, N1_, 1><<<dim3(N1_ / 128, O1_ / 128, B_), 256>>>(p1, b1);
    fin_stats1<<<1, O1_>>>(g1, be1);
    gemm_core<256, 256, N1_, 2><<<dim3(N1_ / 128, 1, B_), 256>>>(nullptr, b2);
    fin_stats2<<<1, O2_>>>(g2, be2);
    finalize<<<(B_ * O2_ * N1_ / 4) / 256, 256>>>(out);
}